// round 10
// baseline (speedup 1.0000x reference)
#include <cuda_runtime.h>
#include <cuda_fp16.h>

// FreqGrid triplane encoder. R10 = R9 + Morton-ordered point processing:
//  - counting sort of points by 12-bit 3D Morton key (4096 cells of 16^3)
//    -> consecutive points in a warp share plane texels -> L1 reuse
//  - gather core unchanged (R5 pipeline, padded grid, fp16 texels, PAIRS=8)
//  - transpose unchanged (swizzled tiles, __ldcs source)

#define RR 256
#define CHN 128
#define PLANE_ELEMS (RR * RR)              // 65536
#define GT_ELEMS (3 * PLANE_ELEMS * CHN)   // 48 MB of halfs
#define GT_PAD (33024)
#define NPTS (1 << 18)                     // 262144
#define NCELLS 4096

__device__ __half g_grid_t[GT_ELEMS + GT_PAD];
__device__ int g_hist[NCELLS];             // zero at module load; re-zeroed by scatter
__device__ int g_cursor[NCELLS];
__device__ int g_perm[NPTS];

#define PI_OVER_R 0.01227184630308513f     // pi/256
#define KC        0.006135923151542565f    // pi/512

// ---------------------------------------------------------------------------
// Morton key: 4 bits per axis interleaved -> 12-bit cell id
// ---------------------------------------------------------------------------
__device__ __forceinline__ int point_key(const float* __restrict__ coords, int n) {
    int cx = min((int)((coords[3 * n + 0] + 1.0f) * 8.0f), 15);
    int cy = min((int)((coords[3 * n + 1] + 1.0f) * 8.0f), 15);
    int cz = min((int)((coords[3 * n + 2] + 1.0f) * 8.0f), 15);
    int k = 0;
    #pragma unroll
    for (int b = 0; b < 4; b++) {
        k |= (((cx >> b) & 1) << (3 * b))
           | (((cy >> b) & 1) << (3 * b + 1))
           | (((cz >> b) & 1) << (3 * b + 2));
    }
    return k;
}

__global__ void __launch_bounds__(256) hist_kernel(const float* __restrict__ coords, int N) {
    int n = blockIdx.x * 256 + threadIdx.x;
    if (n < N) atomicAdd(&g_hist[point_key(coords, n)], 1);
}

__global__ void __launch_bounds__(1024) scan_kernel() {
    __shared__ int a[1024], b[1024];
    int tid = threadIdx.x;
    int base = tid * 4;
    int h0 = g_hist[base], h1 = g_hist[base + 1];
    int h2 = g_hist[base + 2], h3 = g_hist[base + 3];
    int s = h0 + h1 + h2 + h3;
    a[tid] = s;
    __syncthreads();
    int* src = a; int* dst = b;
    for (int off = 1; off < 1024; off <<= 1) {
        int v = src[tid];
        if (tid >= off) v += src[tid - off];
        dst[tid] = v;
        __syncthreads();
        int* t = src; src = dst; dst = t;
    }
    int excl = src[tid] - s;
    g_cursor[base]     = excl;
    g_cursor[base + 1] = excl + h0;
    g_cursor[base + 2] = excl + h0 + h1;
    g_cursor[base + 3] = excl + h0 + h1 + h2;
}

__global__ void __launch_bounds__(256) scatter_kernel(const float* __restrict__ coords, int N) {
    // block 0 re-zeroes g_hist for the next launch (hist is dead after scan)
    if (blockIdx.x == 0) {
        #pragma unroll
        for (int i = 0; i < NCELLS / 256; i++)
            g_hist[threadIdx.x + 256 * i] = 0;
    }
    int n = blockIdx.x * 256 + threadIdx.x;
    if (n < N) {
        int pos = atomicAdd(&g_cursor[point_key(coords, n)], 1);
        g_perm[pos] = n;
    }
}

// ---------------------------------------------------------------------------
// swizzled half-index for (spatial row s, channel ch) in a 64x128 tile
// ---------------------------------------------------------------------------
__device__ __forceinline__ int sw_idx(int s, int ch) {
    int chunk = (ch >> 3) ^ ((s >> 2) & 15);
    return s * 128 + (chunk << 3) + (ch & 7);
}

__global__ void __launch_bounds__(256) transpose_kernel(const float* __restrict__ g) {
    __shared__ __half tile[64 * 128];
    const int p  = blockIdx.y;
    const int s0 = blockIdx.x << 6;
    const int tid = threadIdx.x;

    const float* in = g + (size_t)p * CHN * PLANE_ELEMS + s0;

    #pragma unroll
    for (int i = 0; i < 8; i++) {
        int u  = i * 256 + tid;
        int q  = u & 15;
        int ch = u >> 4;
        float4 f = __ldcs((const float4*)(in + (size_t)ch * PLANE_ELEMS + 4 * q));
        tile[sw_idx(4 * q + 0, ch)] = __float2half_rn(f.x);
        tile[sw_idx(4 * q + 1, ch)] = __float2half_rn(f.y);
        tile[sw_idx(4 * q + 2, ch)] = __float2half_rn(f.z);
        tile[sw_idx(4 * q + 3, ch)] = __float2half_rn(f.w);
    }
    __syncthreads();

    __half* outp = g_grid_t + (size_t)p * PLANE_ELEMS * CHN + (size_t)s0 * CHN;
    #pragma unroll
    for (int i = 0; i < 4; i++) {
        int u  = i * 256 + tid;
        int c8 = u & 15;
        int s  = u >> 4;
        int chunk = c8 ^ ((s >> 2) & 15);
        uint4 val = *(const uint4*)&tile[s * 128 + (chunk << 3)];
        *(uint4*)(outp + s * CHN + 8 * c8) = val;
    }
}

// ---------------------------------------------------------------------------
// Gather + basis: half-warp per point (Morton order), lane owns channel lane&15
// ---------------------------------------------------------------------------
__device__ __forceinline__ void load_corners(const uint4* __restrict__ gb,
                                             int off, uint4* v) {
    v[0] = __ldg(&gb[off]);
    v[1] = __ldg(&gb[off + 16]);
    v[2] = __ldg(&gb[off + 4096]);
    v[3] = __ldg(&gb[off + 4112]);
}

__device__ __forceinline__ void blend_plane(const uint4* v, float wxd, float wyd,
                                            float kdd, const float* frh,
                                            float& acc0, float& acc1) {
    __half2 w00 = __float2half2_rn((1.0f - wxd) * (1.0f - wyd));
    __half2 w01 = __float2half2_rn(wxd * (1.0f - wyd));
    __half2 w10 = __float2half2_rn((1.0f - wxd) * wyd);
    __half2 w11 = __float2half2_rn(wxd * wyd);

    const __half2* c0 = (const __half2*)&v[0];
    const __half2* c1 = (const __half2*)&v[1];
    const __half2* c2 = (const __half2*)&v[2];
    const __half2* c3 = (const __half2*)&v[3];

    #pragma unroll
    for (int q = 0; q < 4; q++) {
        __half2 cf = __hmul2(w00, c0[q]);
        cf = __hfma2(w01, c1[q], cf);
        cf = __hfma2(w10, c2[q], cf);
        cf = __hfma2(w11, c3[q], cf);
        float2 f = __half22float2(cf);
        acc0 = fmaf(f.x, __cosf(kdd * frh[2 * q]),     acc0);
        acc1 = fmaf(f.y, __cosf(kdd * frh[2 * q + 1]), acc1);
    }
}

template <int PAIRS>
__global__ void __launch_bounds__(256)
freqgrid_kernel(const float* __restrict__ coords,
                const float* __restrict__ freqs,
                float* __restrict__ out, int N) {
    const int warp = (blockIdx.x * blockDim.x + threadIdx.x) >> 5;
    const int lane = threadIdx.x & 31;
    const int sub  = lane >> 4;
    const int cl   = lane & 15;

    float frh[8];
    #pragma unroll
    for (int j = 0; j < 8; j++) {
        float fq = __ldg(&freqs[8 * cl + j]);
        fq = fminf(fmaxf(fq, 0.0f), 1.0f);
        frh[j] = exp2f(fq * 8.0f) - 0.5f;
    }

    const uint4* __restrict__ gb = (const uint4*)g_grid_t;
    const int base0 = warp * (2 * PAIRS);

    // prefetch sorted-point ids (cheap: PAIRS ints)
    int pid[PAIRS];
    #pragma unroll
    for (int t = 0; t < PAIRS; t++)
        pid[t] = g_perm[min(base0 + 2 * t + sub, N - 1)];

    #pragma unroll
    for (int t = 0; t < PAIRS; t++) {
        const int i = base0 + 2 * t;
        if (i >= N) return;
        const int n = pid[t];

        float pt0 = fmaf(coords[3 * n + 0], 127.5f, 127.5f);
        float pt1 = fmaf(coords[3 * n + 1], 127.5f, 127.5f);
        float pt2 = fmaf(coords[3 * n + 2], 127.5f, 127.5f);

        float kd0 = fmaf(pt0, PI_OVER_R, KC);
        float kd1 = fmaf(pt1, PI_OVER_R, KC);
        float kd2 = fmaf(pt2, PI_OVER_R, KC);

        int x0a = (int)pt1, y0a = (int)pt2;        // plane 0
        int x0b = (int)pt0, y0b = (int)pt2;        // plane 1
        int x0c = (int)pt0, y0c = (int)pt1;        // plane 2

        float wxa = pt1 - (float)x0a, wya = pt2 - (float)y0a;
        float wxb = pt0 - (float)x0b, wyb = pt2 - (float)y0b;
        float wxc = pt0 - (float)x0c, wyc = pt1 - (float)y0c;

        int offa = (((y0a << 8) + x0a) << 4) + cl;
        int offb = ((PLANE_ELEMS + (y0b << 8) + x0b) << 4) + cl;
        int offc = ((2 * PLANE_ELEMS + (y0c << 8) + x0c) << 4) + cl;

        float acc0 = 0.0f, acc1 = 0.0f;
        uint4 va[4], vb[4];

        load_corners(gb, offa, va);
        load_corners(gb, offb, vb);
        blend_plane(va, wxa, wya, kd0, frh, acc0, acc1);
        load_corners(gb, offc, va);
        blend_plane(vb, wxb, wyb, kd1, frh, acc0, acc1);
        blend_plane(va, wxc, wyc, kd2, frh, acc0, acc1);

        if (i + sub < N) {
            out[n * 16 + cl] = 2.0f * (acc0 + acc1);
        }
    }
}

// ---------------------------------------------------------------------------
// Harness entry
// ---------------------------------------------------------------------------
extern "C" void kernel_launch(void* const* d_in, const int* in_sizes, int n_in,
                              void* d_out, int out_size) {
    const float* coords = (const float*)d_in[0];
    const float* grid   = (const float*)d_in[1];
    const float* freqs  = (const float*)d_in[2];
    float* out = (float*)d_out;

    const int N = in_sizes[0] / 3;
    const int pt_blocks = (N + 255) / 256;

    // grid transpose (independent of the sort chain)
    dim3 tg(PLANE_ELEMS / 64, 3);
    transpose_kernel<<<tg, 256>>>(grid);

    // Morton counting sort: hist -> scan -> scatter (scatter re-zeroes hist)
    hist_kernel<<<pt_blocks, 256>>>(coords, N);
    scan_kernel<<<1, 1024>>>();
    scatter_kernel<<<pt_blocks, 256>>>(coords, N);

    // gather in Morton order
    constexpr int PAIRS = 8;                       // 16 points per warp
    const int pts_per_warp = 2 * PAIRS;
    const int warps = (N + pts_per_warp - 1) / pts_per_warp;
    const int blocks = (warps * 32 + 255) / 256;
    freqgrid_kernel<PAIRS><<<blocks, 256>>>(coords, freqs, out, N);
}

// round 11
// speedup vs baseline: 1.2764x; 1.2764x over previous
#include <cuda_runtime.h>
#include <cuda_fp16.h>

// FreqGrid triplane encoder. R11 = R9 (best: 70.4us) + inner-loop dead-weight
// elimination:
//  - GUARD=false specialization when N % (2*PAIRS) == 0 (it is: 262144):
//    no per-iteration bounds branch, no min(), unconditional store
//  - lane channel offset (cl) hoisted into base pointers
//  - everything else identical: fp16 transposed grid (48 MB, L2-resident),
//    padded (no boundary selects), 2-stage plane pipeline, HFMA2 blend,
//    __ldcs transpose source reads

#define RR 256
#define CHN 128
#define PLANE_ELEMS (RR * RR)              // 65536
#define GT_ELEMS (3 * PLANE_ELEMS * CHN)   // 48 MB of halfs
#define GT_PAD (33024)                     // covers +row+texel overrun (zeroed)

__device__ __half g_grid_t[GT_ELEMS + GT_PAD];

#define PI_OVER_R 0.01227184630308513f     // pi/256
#define KC        0.006135923151542565f    // pi/512

// swizzled half-index for (spatial row s, channel ch) in a 64x128 tile
__device__ __forceinline__ int sw_idx(int s, int ch) {
    int chunk = (ch >> 3) ^ ((s >> 2) & 15);
    return s * 128 + (chunk << 3) + (ch & 7);
}

// ---------------------------------------------------------------------------
// Transpose + quantize: in[p][ch][s] -> g_grid_t[p][s][ch] (fp16)
// ---------------------------------------------------------------------------
__global__ void __launch_bounds__(256) transpose_kernel(const float* __restrict__ g) {
    __shared__ __half tile[64 * 128];
    const int p  = blockIdx.y;
    const int s0 = blockIdx.x << 6;
    const int tid = threadIdx.x;

    const float* in = g + (size_t)p * CHN * PLANE_ELEMS + s0;

    #pragma unroll
    for (int i = 0; i < 8; i++) {
        int u  = i * 256 + tid;
        int q  = u & 15;
        int ch = u >> 4;
        float4 f = __ldcs((const float4*)(in + (size_t)ch * PLANE_ELEMS + 4 * q));
        tile[sw_idx(4 * q + 0, ch)] = __float2half_rn(f.x);
        tile[sw_idx(4 * q + 1, ch)] = __float2half_rn(f.y);
        tile[sw_idx(4 * q + 2, ch)] = __float2half_rn(f.z);
        tile[sw_idx(4 * q + 3, ch)] = __float2half_rn(f.w);
    }
    __syncthreads();

    __half* outp = g_grid_t + (size_t)p * PLANE_ELEMS * CHN + (size_t)s0 * CHN;
    #pragma unroll
    for (int i = 0; i < 4; i++) {
        int u  = i * 256 + tid;
        int c8 = u & 15;
        int s  = u >> 4;
        int chunk = c8 ^ ((s >> 2) & 15);
        uint4 val = *(const uint4*)&tile[s * 128 + (chunk << 3)];
        *(uint4*)(outp + s * CHN + 8 * c8) = val;
    }
}

// ---------------------------------------------------------------------------
// Gather + basis: half-warp per point, lane owns output channel c = lane&15
// ---------------------------------------------------------------------------
__device__ __forceinline__ void load_corners(const uint4* __restrict__ gb,
                                             int off, uint4* v) {
    v[0] = __ldg(&gb[off]);
    v[1] = __ldg(&gb[off + 16]);       // +x texel
    v[2] = __ldg(&gb[off + 4096]);     // +y row
    v[3] = __ldg(&gb[off + 4112]);
}

__device__ __forceinline__ void blend_plane(const uint4* v, float wxd, float wyd,
                                            float kdd, const float* frh,
                                            float& acc0, float& acc1) {
    __half2 w00 = __float2half2_rn((1.0f - wxd) * (1.0f - wyd));
    __half2 w01 = __float2half2_rn(wxd * (1.0f - wyd));
    __half2 w10 = __float2half2_rn((1.0f - wxd) * wyd);
    __half2 w11 = __float2half2_rn(wxd * wyd);

    const __half2* c0 = (const __half2*)&v[0];
    const __half2* c1 = (const __half2*)&v[1];
    const __half2* c2 = (const __half2*)&v[2];
    const __half2* c3 = (const __half2*)&v[3];

    #pragma unroll
    for (int q = 0; q < 4; q++) {
        __half2 cf = __hmul2(w00, c0[q]);
        cf = __hfma2(w01, c1[q], cf);
        cf = __hfma2(w10, c2[q], cf);
        cf = __hfma2(w11, c3[q], cf);
        float2 f = __half22float2(cf);
        acc0 = fmaf(f.x, __cosf(kdd * frh[2 * q]),     acc0);
        acc1 = fmaf(f.y, __cosf(kdd * frh[2 * q + 1]), acc1);
    }
}

template <int PAIRS, bool GUARD>
__global__ void __launch_bounds__(256)
freqgrid_kernel(const float* __restrict__ coords,
                const float* __restrict__ freqs,
                float* __restrict__ out, int N) {
    const int warp = (blockIdx.x * blockDim.x + threadIdx.x) >> 5;
    const int lane = threadIdx.x & 31;
    const int sub  = lane >> 4;     // 0: point A, 1: point B
    const int cl   = lane & 15;     // output channel / uint4 slot

    // Per-lane frequency constants for channels 8*cl + j
    float frh[8];
    #pragma unroll
    for (int j = 0; j < 8; j++) {
        float fq = __ldg(&freqs[8 * cl + j]);
        fq = fminf(fmaxf(fq, 0.0f), 1.0f);
        frh[j] = exp2f(fq * 8.0f) - 0.5f;
    }

    // lane channel offset hoisted into the bases
    const uint4* __restrict__ gb = (const uint4*)g_grid_t + cl;
    float* __restrict__ outl = out + cl;

    const int base0 = warp * (2 * PAIRS);
    #pragma unroll
    for (int t = 0; t < PAIRS; t++) {
        const int nb = base0 + 2 * t;
        if (GUARD) { if (nb >= N) return; }
        const int n = GUARD ? min(nb + sub, N - 1) : (nb + sub);

        float pt0 = fmaf(coords[3 * n + 0], 127.5f, 127.5f);
        float pt1 = fmaf(coords[3 * n + 1], 127.5f, 127.5f);
        float pt2 = fmaf(coords[3 * n + 2], 127.5f, 127.5f);

        float kd0 = fmaf(pt0, PI_OVER_R, KC);
        float kd1 = fmaf(pt1, PI_OVER_R, KC);
        float kd2 = fmaf(pt2, PI_OVER_R, KC);

        // plane d samples (ix,iy) from pt[{1,0,0}], pt[{2,2,1}]
        // coords in [-1,1): top-edge corners carry exactly-zero weights;
        // padded grid makes the unclamped reads safe.
        int x0a = (int)pt1, y0a = (int)pt2;        // plane 0
        int x0b = (int)pt0, y0b = (int)pt2;        // plane 1
        int x0c = (int)pt0, y0c = (int)pt1;        // plane 2

        float wxa = pt1 - (float)x0a, wya = pt2 - (float)y0a;
        float wxb = pt0 - (float)x0b, wyb = pt2 - (float)y0b;
        float wxc = pt0 - (float)x0c, wyc = pt1 - (float)y0c;

        int offa = ((y0a << 8) + x0a) << 4;
        int offb = (PLANE_ELEMS + (y0b << 8) + x0b) << 4;
        int offc = ((2 * PLANE_ELEMS) + (y0c << 8) + x0c) << 4;

        float acc0 = 0.0f, acc1 = 0.0f;
        uint4 va[4], vb[4];

        // 2-deep software pipeline over the 3 planes
        load_corners(gb, offa, va);
        load_corners(gb, offb, vb);
        blend_plane(va, wxa, wya, kd0, frh, acc0, acc1);
        load_corners(gb, offc, va);
        blend_plane(vb, wxb, wyb, kd1, frh, acc0, acc1);
        blend_plane(va, wxc, wyc, kd2, frh, acc0, acc1);

        if (GUARD) {
            if (nb + sub < N) outl[n * 16] = 2.0f * (acc0 + acc1);
        } else {
            outl[n * 16] = 2.0f * (acc0 + acc1);
        }
    }
}

// ---------------------------------------------------------------------------
// Harness entry
// ---------------------------------------------------------------------------
extern "C" void kernel_launch(void* const* d_in, const int* in_sizes, int n_in,
                              void* d_out, int out_size) {
    const float* coords = (const float*)d_in[0];
    const float* grid   = (const float*)d_in[1];
    const float* freqs  = (const float*)d_in[2];
    float* out = (float*)d_out;

    const int N = in_sizes[0] / 3;

    dim3 tg(PLANE_ELEMS / 64, 3);
    transpose_kernel<<<tg, 256>>>(grid);

    constexpr int PAIRS = 8;                       // 16 points per warp
    const int pts_per_warp = 2 * PAIRS;
    const int warps = (N + pts_per_warp - 1) / pts_per_warp;
    const int blocks = (warps * 32 + 255) / 256;

    if (N % pts_per_warp == 0) {
        freqgrid_kernel<PAIRS, false><<<blocks, 256>>>(coords, freqs, out, N);
    } else {
        freqgrid_kernel<PAIRS, true><<<blocks, 256>>>(coords, freqs, out, N);
    }
}

// round 12
// speedup vs baseline: 1.3504x; 1.0579x over previous
#include <cuda_runtime.h>
#include <cuda_fp16.h>

// FreqGrid triplane encoder. R12 = R9 (best: 70.4us) + cache-policy hints ONLY:
//  - output stores via __stcs (write-once, evict-first: don't evict the grid)
//  - coords loads via __ldcs (read-once)
//  - everything else byte-identical to R9: fp16 transposed grid (48 MB,
//    L2-resident), padded grid (no boundary selects), half-warp per point,
//    2-stage plane pipeline, HFMA2 blend, PAIRS=8, __ldcs transpose source.

#define RR 256
#define CHN 128
#define PLANE_ELEMS (RR * RR)              // 65536
#define GT_ELEMS (3 * PLANE_ELEMS * CHN)   // 48 MB of halfs
#define GT_PAD (33024)                     // covers +row+texel overrun (zeroed)

__device__ __half g_grid_t[GT_ELEMS + GT_PAD];

#define PI_OVER_R 0.01227184630308513f     // pi/256
#define KC        0.006135923151542565f    // pi/512

// swizzled half-index for (spatial row s, channel ch) in a 64x128 tile
__device__ __forceinline__ int sw_idx(int s, int ch) {
    int chunk = (ch >> 3) ^ ((s >> 2) & 15);
    return s * 128 + (chunk << 3) + (ch & 7);
}

// ---------------------------------------------------------------------------
// Transpose + quantize: in[p][ch][s] -> g_grid_t[p][s][ch] (fp16)
// ---------------------------------------------------------------------------
__global__ void __launch_bounds__(256) transpose_kernel(const float* __restrict__ g) {
    __shared__ __half tile[64 * 128];
    const int p  = blockIdx.y;
    const int s0 = blockIdx.x << 6;
    const int tid = threadIdx.x;

    const float* in = g + (size_t)p * CHN * PLANE_ELEMS + s0;

    #pragma unroll
    for (int i = 0; i < 8; i++) {
        int u  = i * 256 + tid;
        int q  = u & 15;
        int ch = u >> 4;
        float4 f = __ldcs((const float4*)(in + (size_t)ch * PLANE_ELEMS + 4 * q));
        tile[sw_idx(4 * q + 0, ch)] = __float2half_rn(f.x);
        tile[sw_idx(4 * q + 1, ch)] = __float2half_rn(f.y);
        tile[sw_idx(4 * q + 2, ch)] = __float2half_rn(f.z);
        tile[sw_idx(4 * q + 3, ch)] = __float2half_rn(f.w);
    }
    __syncthreads();

    __half* outp = g_grid_t + (size_t)p * PLANE_ELEMS * CHN + (size_t)s0 * CHN;
    #pragma unroll
    for (int i = 0; i < 4; i++) {
        int u  = i * 256 + tid;
        int c8 = u & 15;
        int s  = u >> 4;
        int chunk = c8 ^ ((s >> 2) & 15);
        uint4 val = *(const uint4*)&tile[s * 128 + (chunk << 3)];
        *(uint4*)(outp + s * CHN + 8 * c8) = val;
    }
}

// ---------------------------------------------------------------------------
// Gather + basis: half-warp per point, lane owns output channel c = lane&15
// ---------------------------------------------------------------------------
__device__ __forceinline__ void load_corners(const uint4* __restrict__ gb,
                                             int off, uint4* v) {
    v[0] = __ldg(&gb[off]);
    v[1] = __ldg(&gb[off + 16]);       // +x texel
    v[2] = __ldg(&gb[off + 4096]);     // +y row
    v[3] = __ldg(&gb[off + 4112]);
}

__device__ __forceinline__ void blend_plane(const uint4* v, float wxd, float wyd,
                                            float kdd, const float* frh,
                                            float& acc0, float& acc1) {
    __half2 w00 = __float2half2_rn((1.0f - wxd) * (1.0f - wyd));
    __half2 w01 = __float2half2_rn(wxd * (1.0f - wyd));
    __half2 w10 = __float2half2_rn((1.0f - wxd) * wyd);
    __half2 w11 = __float2half2_rn(wxd * wyd);

    const __half2* c0 = (const __half2*)&v[0];
    const __half2* c1 = (const __half2*)&v[1];
    const __half2* c2 = (const __half2*)&v[2];
    const __half2* c3 = (const __half2*)&v[3];

    #pragma unroll
    for (int q = 0; q < 4; q++) {
        __half2 cf = __hmul2(w00, c0[q]);
        cf = __hfma2(w01, c1[q], cf);
        cf = __hfma2(w10, c2[q], cf);
        cf = __hfma2(w11, c3[q], cf);
        float2 f = __half22float2(cf);
        acc0 = fmaf(f.x, __cosf(kdd * frh[2 * q]),     acc0);
        acc1 = fmaf(f.y, __cosf(kdd * frh[2 * q + 1]), acc1);
    }
}

template <int PAIRS>
__global__ void __launch_bounds__(256)
freqgrid_kernel(const float* __restrict__ coords,
                const float* __restrict__ freqs,
                float* __restrict__ out, int N) {
    const int warp = (blockIdx.x * blockDim.x + threadIdx.x) >> 5;
    const int lane = threadIdx.x & 31;
    const int sub  = lane >> 4;     // 0: point A, 1: point B
    const int cl   = lane & 15;     // output channel / uint4 slot

    // Per-lane frequency constants for channels 8*cl + j
    float frh[8];
    #pragma unroll
    for (int j = 0; j < 8; j++) {
        float fq = __ldg(&freqs[8 * cl + j]);
        fq = fminf(fmaxf(fq, 0.0f), 1.0f);
        frh[j] = exp2f(fq * 8.0f) - 0.5f;
    }

    const uint4* __restrict__ gb = (const uint4*)g_grid_t;   // texel = 16 uint4

    const int base0 = warp * (2 * PAIRS);
    #pragma unroll
    for (int t = 0; t < PAIRS; t++) {
        const int nb = base0 + 2 * t;
        if (nb >= N) return;
        const int n = min(nb + sub, N - 1);

        // read-once coords: streaming loads (don't displace grid texels in L2)
        float pt0 = fmaf(__ldcs(&coords[3 * n + 0]), 127.5f, 127.5f);
        float pt1 = fmaf(__ldcs(&coords[3 * n + 1]), 127.5f, 127.5f);
        float pt2 = fmaf(__ldcs(&coords[3 * n + 2]), 127.5f, 127.5f);

        float kd0 = fmaf(pt0, PI_OVER_R, KC);
        float kd1 = fmaf(pt1, PI_OVER_R, KC);
        float kd2 = fmaf(pt2, PI_OVER_R, KC);

        // plane d samples (ix,iy) from pt[{1,0,0}], pt[{2,2,1}]
        // coords in [-1,1): top-edge corners carry exactly-zero weights;
        // padded grid makes the unclamped reads safe.
        int x0a = (int)pt1, y0a = (int)pt2;        // plane 0
        int x0b = (int)pt0, y0b = (int)pt2;        // plane 1
        int x0c = (int)pt0, y0c = (int)pt1;        // plane 2

        float wxa = pt1 - (float)x0a, wya = pt2 - (float)y0a;
        float wxb = pt0 - (float)x0b, wyb = pt2 - (float)y0b;
        float wxc = pt0 - (float)x0c, wyc = pt1 - (float)y0c;

        int offa = (((y0a << 8) + x0a) << 4) + cl;
        int offb = ((PLANE_ELEMS + (y0b << 8) + x0b) << 4) + cl;
        int offc = ((2 * PLANE_ELEMS + (y0c << 8) + x0c) << 4) + cl;

        float acc0 = 0.0f, acc1 = 0.0f;
        uint4 va[4], vb[4];

        // 2-deep software pipeline over the 3 planes
        load_corners(gb, offa, va);
        load_corners(gb, offb, vb);
        blend_plane(va, wxa, wya, kd0, frh, acc0, acc1);
        load_corners(gb, offc, va);
        blend_plane(vb, wxb, wyb, kd1, frh, acc0, acc1);
        blend_plane(va, wxc, wyc, kd2, frh, acc0, acc1);

        if (nb + sub < N) {
            // write-once output: streaming store, keep grid resident in L2
            __stcs(&out[n * 16 + cl], 2.0f * (acc0 + acc1));
        }
    }
}

// ---------------------------------------------------------------------------
// Harness entry
// ---------------------------------------------------------------------------
extern "C" void kernel_launch(void* const* d_in, const int* in_sizes, int n_in,
                              void* d_out, int out_size) {
    const float* coords = (const float*)d_in[0];
    const float* grid   = (const float*)d_in[1];
    const float* freqs  = (const float*)d_in[2];
    float* out = (float*)d_out;

    const int N = in_sizes[0] / 3;

    dim3 tg(PLANE_ELEMS / 64, 3);
    transpose_kernel<<<tg, 256>>>(grid);

    constexpr int PAIRS = 8;                       // 16 points per warp
    const int pts_per_warp = 2 * PAIRS;
    const int warps = (N + pts_per_warp - 1) / pts_per_warp;
    const int blocks = (warps * 32 + 255) / 256;
    freqgrid_kernel<PAIRS><<<blocks, 256>>>(coords, freqs, out, N);
}